// round 5
// baseline (speedup 1.0000x reference)
#include <cuda_runtime.h>
#include <cstdint>
#include <math.h>

#define NHEADS 16
#define SEQ    2048
#define EMB    1024
#define NBATCH 2
#define DHEAD  64

// Scratch (allocation-free rule): device globals.
__device__ float g_q[NBATCH * NHEADS * SEQ * DHEAD];
__device__ float g_k[NBATCH * NHEADS * SEQ * DHEAD];
__device__ float g_v[NBATCH * NHEADS * SEQ * DHEAD];
__device__ float g_ctx[NBATCH * SEQ * EMB];
// Pre-rounded (tf32-grid) copies of inputs.
__device__ float g_xr[NBATCH * SEQ * EMB];
__device__ float g_wk[EMB * EMB];
__device__ float g_wq[EMB * EMB];
__device__ float g_wv[EMB * EMB];
__device__ float g_wu[EMB * EMB];

// ===========================================================================
// helpers
// ===========================================================================
__device__ __forceinline__ uint32_t f2tf32(float f) {
    uint32_t u;
    asm("cvt.rna.tf32.f32 %0, %1;" : "=r"(u) : "f"(f));
    return u;
}
__device__ __forceinline__ float rna32(float f) { return __uint_as_float(f2tf32(f)); }
__device__ __forceinline__ void mma_tf32(float c[4], const uint32_t a[4], const uint32_t b[2]) {
    asm volatile(
        "mma.sync.aligned.m16n8k8.row.col.f32.tf32.tf32.f32 "
        "{%0,%1,%2,%3}, {%4,%5,%6,%7}, {%8,%9}, {%0,%1,%2,%3};"
        : "+f"(c[0]), "+f"(c[1]), "+f"(c[2]), "+f"(c[3])
        : "r"(a[0]), "r"(a[1]), "r"(a[2]), "r"(a[3]), "r"(b[0]), "r"(b[1]));
}
__device__ __forceinline__ void cp16(uint32_t saddr, const void* gptr) {
    asm volatile("cp.async.cg.shared.global [%0], [%1], 16;" :: "r"(saddr), "l"(gptr));
}
#define CP_COMMIT() asm volatile("cp.async.commit_group;" ::: "memory")
#define CP_WAIT(n)  asm volatile("cp.async.wait_group %0;" :: "n"(n) : "memory")
__device__ __forceinline__ uint32_t smem_u32(const void* p) {
    uint32_t a;
    asm("{ .reg .u64 t; cvta.to.shared.u64 t, %1; cvt.u32.u64 %0, t; }" : "=r"(a) : "l"(p));
    return a;
}

// ===========================================================================
// Pre-round inputs to tf32 grid (RNA). i < 1M float4 -> x; then 256K per W.
// ===========================================================================
__global__ __launch_bounds__(256) void preround(const float4* __restrict__ x,
                                                const float4* __restrict__ wk,
                                                const float4* __restrict__ wq,
                                                const float4* __restrict__ wv,
                                                const float4* __restrict__ wu) {
    int i = blockIdx.x * 256 + threadIdx.x;
    const float4* src;
    float4* dst;
    if (i < 1048576) {
        src = x + i;
        dst = (float4*)g_xr + i;
    } else {
        int j = i - 1048576;
        int w = j >> 18;
        int l = j & 262143;
        if (w == 0)      { src = wk + l; dst = (float4*)g_wk + l; }
        else if (w == 1) { src = wq + l; dst = (float4*)g_wq + l; }
        else if (w == 2) { src = wv + l; dst = (float4*)g_wv + l; }
        else             { src = wu + l; dst = (float4*)g_wu + l; }
    }
    float4 v = *src;
    *dst = make_float4(rna32(v.x), rna32(v.y), rna32(v.z), rna32(v.w));
}

// ===========================================================================
// Tensor-core NT GEMM: C[m,n] = sum_k A[m,k]*B[n,k].  M=4096, N=1024, K=1024.
// Inputs pre-rounded to tf32 grid -> cp.async raw bits DIRECTLY into the
// (round-3-validated) fragment layout. 3-stage pipeline, no cvt in hot loop.
//   fragA[mt][s][reg][lane] (16KB/stage), fragB[nt][s][reg][lane] (16KB/stage)
// MODE 0: scatter C into [B,H,S,D], rounded to tf32 grid.
// MODE 1: row-major + bias (fp32).
// ===========================================================================
#define GK          1024
#define KT          32
#define NKT         (GK / KT)
#define STAGE_FLT   8192
#define STAGE_BYTES (STAGE_FLT * 4)
#define NSTAGE      3
#define GEMM_SMEM   (NSTAGE * STAGE_BYTES)   // 98304

__device__ __forceinline__ void gemm_issue(uint32_t smb, int kt,
                                           const float* Ap0, const float* Bp0,
                                           const int offA[4], const int offB[4]) {
    uint32_t base = smb + (kt % NSTAGE) * STAGE_BYTES;
    const float* Ap = Ap0 + kt * KT;
    const float* Bp = Bp0 + kt * KT;
#pragma unroll
    for (int j = 0; j < 4; j++) {
        cp16(base + offA[j] * 4, Ap + j * 4);
        cp16(base + offB[j] * 4, Bp + j * 4);
    }
}

template <int MODE>
__global__ __launch_bounds__(256) void gemm_tc(const float* __restrict__ A,
                                               const float* __restrict__ Bm,
                                               float* __restrict__ C,
                                               const float* __restrict__ bias) {
    extern __shared__ float smf[];
    const uint32_t smb = smem_u32(smf);
    const int tid = threadIdx.x;
    const int wid = tid >> 5;
    const int lane = tid & 31;
    const int m0 = blockIdx.y * 128;
    const int n0 = blockIdx.x * 128;
    const int wm = (wid >> 2) * 64;
    const int wn = (wid & 3) * 32;

    const int lr = tid >> 1;
    const int lkb = (tid & 1) * 16;
    const float* Ap0 = A  + (size_t)(m0 + lr) * GK + lkb;
    const float* Bp0 = Bm + (size_t)(n0 + lr) * GK + lkb;

    int offA[4], offB[4];
#pragma unroll
    for (int j = 0; j < 4; j++) {
        int k = lkb + j * 4;
        int s = k >> 3;
        int half = (k >> 2) & 1;
        {
            int mt = lr >> 4, rr = lr & 15, g = rr & 7;
            int reg = (rr >> 3) + half * 2;
            offA[j] = ((mt * 4 + s) * 4 + reg) * 32 + g * 4;
        }
        {
            int nt = lr >> 3, g = lr & 7;
            offB[j] = 4096 + ((nt * 4 + s) * 2 + half) * 32 + g * 4;
        }
    }

    float acc[4][4][4];
#pragma unroll
    for (int i = 0; i < 4; i++)
#pragma unroll
        for (int j = 0; j < 4; j++)
#pragma unroll
            for (int r = 0; r < 4; r++) acc[i][j][r] = 0.f;

    gemm_issue(smb, 0, Ap0, Bp0, offA, offB);
    CP_COMMIT();
    gemm_issue(smb, 1, Ap0, Bp0, offA, offB);
    CP_COMMIT();

    const int mtg0 = wm >> 4;
    const int ntg0 = wn >> 3;

    for (int kt = 0; kt < NKT; kt++) {
        CP_WAIT(1);
        __syncthreads();
        if (kt + 2 < NKT) gemm_issue(smb, kt + 2, Ap0, Bp0, offA, offB);
        CP_COMMIT();   // empty group when no issue keeps the count uniform

        const float* buf = smf + (kt % NSTAGE) * STAGE_FLT;
#pragma unroll
        for (int s = 0; s < 4; s++) {
            uint32_t afr[4][4], bfr[4][2];
#pragma unroll
            for (int mt = 0; mt < 4; mt++) {
                const float* base = buf + ((mtg0 + mt) * 4 + s) * 4 * 32;
#pragma unroll
                for (int r = 0; r < 4; r++)
                    afr[mt][r] = __float_as_uint(base[r * 32 + lane]);
            }
#pragma unroll
            for (int nt = 0; nt < 4; nt++) {
                const float* base = buf + 4096 + ((ntg0 + nt) * 4 + s) * 2 * 32;
#pragma unroll
                for (int r = 0; r < 2; r++)
                    bfr[nt][r] = __float_as_uint(base[r * 32 + lane]);
            }
#pragma unroll
            for (int mt = 0; mt < 4; mt++)
#pragma unroll
                for (int nt = 0; nt < 4; nt++)
                    mma_tf32(acc[mt][nt], afr[mt], bfr[nt]);
        }
    }

    const int g = lane >> 2;
    const int tg = lane & 3;
#pragma unroll
    for (int mt = 0; mt < 4; mt++) {
#pragma unroll
        for (int rh = 0; rh < 2; rh++) {
            const int m = m0 + wm + mt * 16 + g + rh * 8;
#pragma unroll
            for (int nt = 0; nt < 4; nt++) {
                const int n = n0 + wn + nt * 8 + tg * 2;
                float v0 = acc[mt][nt][rh * 2 + 0];
                float v1 = acc[mt][nt][rh * 2 + 1];
                if (MODE == 0) {
                    const int bb = m >> 11, ss = m & 2047;
                    const int hh = n >> 6,  dd = n & 63;
                    float* dst = C + (((size_t)bb * NHEADS + hh) * SEQ + ss) * DHEAD + dd;
                    *(float2*)dst = make_float2(rna32(v0), rna32(v1));
                } else {
                    float* dst = C + (size_t)m * EMB + n;
                    *(float2*)dst = make_float2(v0 + bias[n], v1 + bias[n + 1]);
                }
            }
        }
    }
}

// ===========================================================================
// Tensor-core causal flash attention, MT=2 (32 Q rows / warp).
// CTA = 256 Q rows, 8 warps. KV tiles of 64 double-buffered via cp.async.
// K/V consumed as (truncation-exact, pre-rounded) tf32 B-fragments shared
// across both m16 tiles. ctx written rounded to tf32 grid.
// ===========================================================================
#define KLD 68
#define VLD 72
#define PLD 68
#define K_OFF(p) ((p) * (64 * KLD))
#define V_OFF(p) (2 * 64 * KLD + (p) * (64 * VLD))
#define P_OFF(w) (2 * 64 * KLD + 2 * 64 * VLD + (w) * (32 * PLD))
#define ATTN_SMEM ((2 * 64 * KLD + 2 * 64 * VLD + 8 * 32 * PLD) * 4)

__device__ __forceinline__ void attn_load_tile(uint32_t smbase, int tid, int buf,
                                               const float* kb, const float* vb) {
    uint32_t kdst = smbase + K_OFF(buf) * 4;
    uint32_t vdst = smbase + V_OFF(buf) * 4;
#pragma unroll
    for (int it = 0; it < 4; it++) {
        int id = tid + it * 256;
        int r = id >> 4;
        int c4 = (id & 15) * 4;
        cp16(kdst + (r * KLD + c4) * 4, kb + r * DHEAD + c4);
        cp16(vdst + (r * VLD + c4) * 4, vb + r * DHEAD + c4);
    }
    CP_COMMIT();
}

__global__ __launch_bounds__(256) void attn_tc(const float* __restrict__ Q,
                                               const float* __restrict__ Kg,
                                               const float* __restrict__ Vg,
                                               float* __restrict__ ctx) {
    extern __shared__ float smf[];
    const uint32_t smbase = smem_u32(smf);
    const int tid  = threadIdx.x;
    const int wid  = tid >> 5;
    const int lane = tid & 31;
    const int g    = lane >> 2;
    const int tg   = lane & 3;
    const int blkE = gridDim.x - 1 - blockIdx.x;   // heavy blocks first
    const int h = blockIdx.y;
    const int b = blockIdx.z;
    const int wrow = blkE * 256 + wid * 32;        // warp's first Q row

    const float* qb  = Q  + (((size_t)b * NHEADS + h) * SEQ + wrow) * DHEAD;
    const float* kb0 = Kg + (((size_t)b * NHEADS + h) * SEQ) * DHEAD;
    const float* vb0 = Vg + (((size_t)b * NHEADS + h) * SEQ) * DHEAD;

    // Q A-fragments for 2 m16 tiles, pre-scaled by 1/sqrt(D) (exact pow2)
    uint32_t qf[2][8][4];
#pragma unroll
    for (int mt = 0; mt < 2; mt++) {
        const float* qm = qb + (size_t)mt * 16 * DHEAD;
#pragma unroll
        for (int kk = 0; kk < 8; kk++) {
            qf[mt][kk][0] = __float_as_uint(0.125f * qm[(size_t)g * DHEAD + kk * 8 + tg]);
            qf[mt][kk][1] = __float_as_uint(0.125f * qm[(size_t)(g + 8) * DHEAD + kk * 8 + tg]);
            qf[mt][kk][2] = __float_as_uint(0.125f * qm[(size_t)g * DHEAD + kk * 8 + tg + 4]);
            qf[mt][kk][3] = __float_as_uint(0.125f * qm[(size_t)(g + 8) * DHEAD + kk * 8 + tg + 4]);
        }
    }

    float oacc[2][8][4];
#pragma unroll
    for (int mt = 0; mt < 2; mt++)
#pragma unroll
        for (int nt = 0; nt < 8; nt++)
#pragma unroll
            for (int r = 0; r < 4; r++) oacc[mt][nt][r] = 0.f;
    float m_[2][2] = {{-1e30f, -1e30f}, {-1e30f, -1e30f}};
    float l_[2][2] = {{0.f, 0.f}, {0.f, 0.f}};

    const int nT = 4 * blkE + 4;
    attn_load_tile(smbase, tid, 0, kb0, vb0);

    for (int jt = 0; jt < nT; jt++) {
        const int p = jt & 1;
        if (jt + 1 < nT) {
            attn_load_tile(smbase, tid, 1 - p,
                           kb0 + (size_t)(jt + 1) * 64 * DHEAD,
                           vb0 + (size_t)(jt + 1) * 64 * DHEAD);
            CP_WAIT(1);
        } else {
            CP_WAIT(0);
        }
        __syncthreads();

        if (jt * 64 <= wrow + 31) {
            const float* Ks = smf + K_OFF(p);
            const float* Vs = smf + V_OFF(p);
            float* Ps = smf + P_OFF(wid);

            // ---- S = Q K^T (scaled) ----
            float sacc[2][8][4];
#pragma unroll
            for (int mt = 0; mt < 2; mt++)
#pragma unroll
                for (int nt = 0; nt < 8; nt++)
#pragma unroll
                    for (int r = 0; r < 4; r++) sacc[mt][nt][r] = 0.f;

#pragma unroll
            for (int nt = 0; nt < 8; nt++) {
                const float* krow = Ks + (nt * 8 + g) * KLD;
#pragma unroll
                for (int kk = 0; kk < 8; kk++) {
                    uint32_t bb[2];
                    bb[0] = __float_as_uint(krow[kk * 8 + tg]);
                    bb[1] = __float_as_uint(krow[kk * 8 + tg + 4]);
                    mma_tf32(sacc[0][nt], qf[0][kk], bb);
                    mma_tf32(sacc[1][nt], qf[1][kk], bb);
                }
            }

            // ---- causal mask (diagonal region) ----
            if (jt * 64 + 63 > wrow) {
#pragma unroll
                for (int mt = 0; mt < 2; mt++) {
#pragma unroll
                    for (int nt = 0; nt < 8; nt++) {
                        int colb = jt * 64 + nt * 8 + 2 * tg;
#pragma unroll
                        for (int rh = 0; rh < 2; rh++) {
                            int row = wrow + mt * 16 + g + 8 * rh;
                            if (colb > row)     sacc[mt][nt][rh * 2 + 0] = -1e30f;
                            if (colb + 1 > row) sacc[mt][nt][rh * 2 + 1] = -1e30f;
                        }
                    }
                }
            }

            // ---- online softmax ----
#pragma unroll
            for (int mt = 0; mt < 2; mt++) {
                float rmax[2] = {-1e30f, -1e30f};
#pragma unroll
                for (int nt = 0; nt < 8; nt++)
#pragma unroll
                    for (int rh = 0; rh < 2; rh++)
                        rmax[rh] = fmaxf(rmax[rh],
                                         fmaxf(sacc[mt][nt][rh * 2], sacc[mt][nt][rh * 2 + 1]));
#pragma unroll
                for (int rh = 0; rh < 2; rh++) {
                    rmax[rh] = fmaxf(rmax[rh], __shfl_xor_sync(0xffffffffu, rmax[rh], 1));
                    rmax[rh] = fmaxf(rmax[rh], __shfl_xor_sync(0xffffffffu, rmax[rh], 2));
                }
                float alpha[2], rsum[2] = {0.f, 0.f};
#pragma unroll
                for (int rh = 0; rh < 2; rh++) {
                    float mnew = fmaxf(m_[mt][rh], rmax[rh]);
                    alpha[rh] = __expf(m_[mt][rh] - mnew);
                    m_[mt][rh] = mnew;
                }
#pragma unroll
                for (int nt = 0; nt < 8; nt++)
#pragma unroll
                    for (int rh = 0; rh < 2; rh++) {
                        float p0 = __expf(sacc[mt][nt][rh * 2 + 0] - m_[mt][rh]);
                        float p1 = __expf(sacc[mt][nt][rh * 2 + 1] - m_[mt][rh]);
                        sacc[mt][nt][rh * 2 + 0] = p0;
                        sacc[mt][nt][rh * 2 + 1] = p1;
                        rsum[rh] += p0 + p1;
                    }
#pragma unroll
                for (int rh = 0; rh < 2; rh++) {
                    rsum[rh] += __shfl_xor_sync(0xffffffffu, rsum[rh], 1);
                    rsum[rh] += __shfl_xor_sync(0xffffffffu, rsum[rh], 2);
                    l_[mt][rh] = l_[mt][rh] * alpha[rh] + rsum[rh];
                }
#pragma unroll
                for (int nt = 0; nt < 8; nt++)
#pragma unroll
                    for (int rh = 0; rh < 2; rh++) {
                        oacc[mt][nt][rh * 2 + 0] *= alpha[rh];
                        oacc[mt][nt][rh * 2 + 1] *= alpha[rh];
                    }
            }

            // ---- P -> per-warp smem (RNA tf32 bits) ----
#pragma unroll
            for (int mt = 0; mt < 2; mt++)
#pragma unroll
                for (int nt = 0; nt < 8; nt++) {
                    uint2 u0 = make_uint2(f2tf32(sacc[mt][nt][0]), f2tf32(sacc[mt][nt][1]));
                    uint2 u1 = make_uint2(f2tf32(sacc[mt][nt][2]), f2tf32(sacc[mt][nt][3]));
                    *(uint2*)&Ps[(mt * 16 + g) * PLD + nt * 8 + 2 * tg] = u0;
                    *(uint2*)&Ps[(mt * 16 + g + 8) * PLD + nt * 8 + 2 * tg] = u1;
                }
            __syncwarp();

            // ---- O += P V (V b-frags shared across both m-tiles) ----
#pragma unroll
            for (int kkc = 0; kkc < 8; kkc++) {
                uint32_t a[2][4];
#pragma unroll
                for (int mt = 0; mt < 2; mt++) {
                    a[mt][0] = __float_as_uint(Ps[(mt * 16 + g) * PLD + kkc * 8 + tg]);
                    a[mt][1] = __float_as_uint(Ps[(mt * 16 + g + 8) * PLD + kkc * 8 + tg]);
                    a[mt][2] = __float_as_uint(Ps[(mt * 16 + g) * PLD + kkc * 8 + tg + 4]);
                    a[mt][3] = __float_as_uint(Ps[(mt * 16 + g + 8) * PLD + kkc * 8 + tg + 4]);
                }
                const float* v0 = Vs + (kkc * 8 + tg) * VLD;
                const float* v1 = Vs + (kkc * 8 + tg + 4) * VLD;
#pragma unroll
                for (int ntd = 0; ntd < 8; ntd++) {
                    uint32_t bb[2];
                    bb[0] = __float_as_uint(v0[ntd * 8 + g]);
                    bb[1] = __float_as_uint(v1[ntd * 8 + g]);
                    mma_tf32(oacc[0][ntd], a[0], bb);
                    mma_tf32(oacc[1][ntd], a[1], bb);
                }
            }
        }
        __syncthreads();
    }

    // ---- epilogue: O / l -> ctx [B,S,E], rounded to tf32 grid ----
#pragma unroll
    for (int mt = 0; mt < 2; mt++) {
        float inv[2] = {1.f / l_[mt][0], 1.f / l_[mt][1]};
#pragma unroll
        for (int rh = 0; rh < 2; rh++) {
            const int r = wrow + mt * 16 + g + 8 * rh;
            float* dst = ctx + ((size_t)b * SEQ + r) * EMB + h * DHEAD + 2 * tg;
#pragma unroll
            for (int nt = 0; nt < 8; nt++) {
                float2 v = make_float2(rna32(oacc[mt][nt][rh * 2 + 0] * inv[rh]),
                                       rna32(oacc[mt][nt][rh * 2 + 1] * inv[rh]));
                *(float2*)(dst + nt * 8) = v;
            }
        }
    }
}

// ---------------------------------------------------------------------------
extern "C" void kernel_launch(void* const* d_in, const int* in_sizes, int n_in,
                              void* d_out, int out_size) {
    const float* x  = (const float*)d_in[0];
    const float* Wk = (const float*)d_in[1];
    const float* Wq = (const float*)d_in[2];
    const float* Wv = (const float*)d_in[3];
    const float* Wu = (const float*)d_in[4];
    const float* bu = (const float*)d_in[5];
    float* out = (float*)d_out;

    float *qp, *kp, *vp, *cp, *xr, *wk, *wq, *wv, *wu;
    cudaGetSymbolAddress((void**)&qp, g_q);
    cudaGetSymbolAddress((void**)&kp, g_k);
    cudaGetSymbolAddress((void**)&vp, g_v);
    cudaGetSymbolAddress((void**)&cp, g_ctx);
    cudaGetSymbolAddress((void**)&xr, g_xr);
    cudaGetSymbolAddress((void**)&wk, g_wk);
    cudaGetSymbolAddress((void**)&wq, g_wq);
    cudaGetSymbolAddress((void**)&wv, g_wv);
    cudaGetSymbolAddress((void**)&wu, g_wu);

    cudaFuncSetAttribute(gemm_tc<0>, cudaFuncAttributeMaxDynamicSharedMemorySize, GEMM_SMEM);
    cudaFuncSetAttribute(gemm_tc<1>, cudaFuncAttributeMaxDynamicSharedMemorySize, GEMM_SMEM);
    cudaFuncSetAttribute(attn_tc, cudaFuncAttributeMaxDynamicSharedMemorySize, ATTN_SMEM);

    preround<<<8192, 256>>>((const float4*)x, (const float4*)Wk, (const float4*)Wq,
                            (const float4*)Wv, (const float4*)Wu);

    dim3 gg(EMB / 128, (NBATCH * SEQ) / 128);  // (8, 32)
    gemm_tc<0><<<gg, 256, GEMM_SMEM>>>(xr, wq, qp, nullptr);
    gemm_tc<0><<<gg, 256, GEMM_SMEM>>>(xr, wk, kp, nullptr);
    gemm_tc<0><<<gg, 256, GEMM_SMEM>>>(xr, wv, vp, nullptr);

    attn_tc<<<dim3(SEQ / 256, NHEADS, NBATCH), 256, ATTN_SMEM>>>(qp, kp, vp, cp);

    gemm_tc<1><<<gg, 256, GEMM_SMEM>>>(cp, wu, out, bu);
}

// round 6
// speedup vs baseline: 1.0039x; 1.0039x over previous
#include <cuda_runtime.h>
#include <cstdint>
#include <math.h>

#define NHEADS 16
#define SEQ    2048
#define EMB    1024
#define NBATCH 2
#define DHEAD  64

// Scratch (allocation-free rule): device globals.
__device__ float g_q[NBATCH * NHEADS * SEQ * DHEAD];
__device__ float g_k[NBATCH * NHEADS * SEQ * DHEAD];
__device__ float g_v[NBATCH * NHEADS * SEQ * DHEAD];
__device__ float g_ctx[NBATCH * SEQ * EMB];
// Pre-rounded (tf32-grid) copies of inputs.
__device__ float g_xr[NBATCH * SEQ * EMB];
__device__ float g_wk[EMB * EMB];
__device__ float g_wq[EMB * EMB];
__device__ float g_wv[EMB * EMB];
__device__ float g_wu[EMB * EMB];

// ===========================================================================
// helpers
// ===========================================================================
__device__ __forceinline__ uint32_t f2tf32(float f) {
    uint32_t u;
    asm("cvt.rna.tf32.f32 %0, %1;" : "=r"(u) : "f"(f));
    return u;
}
__device__ __forceinline__ float rna32(float f) { return __uint_as_float(f2tf32(f)); }
__device__ __forceinline__ void mma_tf32(float c[4], const uint32_t a[4], const uint32_t b[2]) {
    asm volatile(
        "mma.sync.aligned.m16n8k8.row.col.f32.tf32.tf32.f32 "
        "{%0,%1,%2,%3}, {%4,%5,%6,%7}, {%8,%9}, {%0,%1,%2,%3};"
        : "+f"(c[0]), "+f"(c[1]), "+f"(c[2]), "+f"(c[3])
        : "r"(a[0]), "r"(a[1]), "r"(a[2]), "r"(a[3]), "r"(b[0]), "r"(b[1]));
}
__device__ __forceinline__ void cp16(uint32_t saddr, const void* gptr) {
    asm volatile("cp.async.cg.shared.global [%0], [%1], 16;" :: "r"(saddr), "l"(gptr));
}
#define CP_COMMIT() asm volatile("cp.async.commit_group;" ::: "memory")
#define CP_WAIT(n)  asm volatile("cp.async.wait_group %0;" :: "n"(n) : "memory")
__device__ __forceinline__ uint32_t smem_u32(const void* p) {
    uint32_t a;
    asm("{ .reg .u64 t; cvta.to.shared.u64 t, %1; cvt.u32.u64 %0, t; }" : "=r"(a) : "l"(p));
    return a;
}

// ===========================================================================
// Pre-round inputs to tf32 grid (RNA).
// ===========================================================================
__global__ __launch_bounds__(256) void preround(const float4* __restrict__ x,
                                                const float4* __restrict__ wk,
                                                const float4* __restrict__ wq,
                                                const float4* __restrict__ wv,
                                                const float4* __restrict__ wu) {
    int i = blockIdx.x * 256 + threadIdx.x;
    const float4* src;
    float4* dst;
    if (i < 1048576) {
        src = x + i;
        dst = (float4*)g_xr + i;
    } else {
        int j = i - 1048576;
        int w = j >> 18;
        int l = j & 262143;
        if (w == 0)      { src = wk + l; dst = (float4*)g_wk + l; }
        else if (w == 1) { src = wq + l; dst = (float4*)g_wq + l; }
        else if (w == 2) { src = wv + l; dst = (float4*)g_wv + l; }
        else             { src = wu + l; dst = (float4*)g_wu + l; }
    }
    float4 v = *src;
    *dst = make_float4(rna32(v.x), rna32(v.y), rna32(v.z), rna32(v.w));
}

// ===========================================================================
// Tensor-core NT GEMM: C[m,n] = sum_k A[m,k]*B[n,k].  M=4096, N=1024, K=1024.
// Pre-rounded inputs -> cp.async raw bits directly into fragment layout.
// CTA 128x128, 4 warps (warp tile 64x64), K-chunk 32, 3-stage pipeline with
// 2 load-groups in flight during compute.
//   fragA[mt8][s4][reg4][lane32] (16KB/stage), fragB[nt16][s4][reg2][lane32]
// MODE 0: scatter C into [B,H,S,D], rounded to tf32 grid.
// MODE 1: row-major + bias (fp32).
// ===========================================================================
#define GK          1024
#define KT          32
#define NKT         (GK / KT)
#define STAGE_FLT   8192
#define STAGE_BYTES (STAGE_FLT * 4)
#define NSTAGE      3
#define GEMM_SMEM   (NSTAGE * STAGE_BYTES)   // 98304

__device__ __forceinline__ void gemm_issue(uint32_t smb, int kt,
                                           const float* Ap0, const float* Bp0,
                                           const int offA[8], const int offB[8]) {
    uint32_t base = smb + (kt % NSTAGE) * STAGE_BYTES;
    const float* Ap = Ap0 + kt * KT;
    const float* Bp = Bp0 + kt * KT;
#pragma unroll
    for (int j = 0; j < 8; j++) {
        cp16(base + offA[j] * 4, Ap + j * 4);
        cp16(base + offB[j] * 4, Bp + j * 4);
    }
}

template <int MODE>
__global__ __launch_bounds__(128) void gemm_tc(const float* __restrict__ A,
                                               const float* __restrict__ Bm,
                                               float* __restrict__ C,
                                               const float* __restrict__ bias) {
    extern __shared__ float smf[];
    const uint32_t smb = smem_u32(smf);
    const int tid = threadIdx.x;
    const int wid = tid >> 5;
    const int lane = tid & 31;
    const int m0 = blockIdx.y * 128;
    const int n0 = blockIdx.x * 128;
    const int wm = (wid >> 1) * 64;   // 0 or 64
    const int wn = (wid & 1) * 64;    // 0 or 64

    // loader: thread lr = tid loads one full 32-float row of A and of B
    const int lr = tid;
    const float* Ap0 = A  + (size_t)(m0 + lr) * GK;
    const float* Bp0 = Bm + (size_t)(n0 + lr) * GK;

    int offA[8], offB[8];
#pragma unroll
    for (int j = 0; j < 8; j++) {
        int s = j >> 1;
        int half = j & 1;
        {
            int mt = lr >> 4, rr = lr & 15, g = rr & 7;
            int reg = (rr >> 3) + half * 2;
            offA[j] = ((mt * 4 + s) * 4 + reg) * 32 + g * 4;
        }
        {
            int nt = lr >> 3, g = lr & 7;
            offB[j] = 4096 + ((nt * 4 + s) * 2 + half) * 32 + g * 4;
        }
    }

    float acc[4][8][4];
#pragma unroll
    for (int i = 0; i < 4; i++)
#pragma unroll
        for (int j = 0; j < 8; j++)
#pragma unroll
            for (int r = 0; r < 4; r++) acc[i][j][r] = 0.f;

    gemm_issue(smb, 0, Ap0, Bp0, offA, offB);
    CP_COMMIT();
    gemm_issue(smb, 1, Ap0, Bp0, offA, offB);
    CP_COMMIT();

    const int mtg0 = wm >> 4;   // 4 m16 tiles
    const int ntg0 = wn >> 3;   // 8 n8 tiles

    for (int kt = 0; kt < NKT; kt++) {
        // stage (kt+2)%3 was computed in iter kt-1; trailing sync freed it.
        if (kt + 2 < NKT) gemm_issue(smb, kt + 2, Ap0, Bp0, offA, offB);
        CP_COMMIT();                  // uniform group count (empty near tail)
        CP_WAIT(2);                   // group kt complete; 2 groups in flight
        __syncthreads();

        const float* buf = smf + (kt % NSTAGE) * STAGE_FLT;
#pragma unroll
        for (int s = 0; s < 4; s++) {
            uint32_t afr[4][4], bfr[8][2];
#pragma unroll
            for (int mt = 0; mt < 4; mt++) {
                const float* base = buf + ((mtg0 + mt) * 4 + s) * 4 * 32;
#pragma unroll
                for (int r = 0; r < 4; r++)
                    afr[mt][r] = __float_as_uint(base[r * 32 + lane]);
            }
#pragma unroll
            for (int nt = 0; nt < 8; nt++) {
                const float* base = buf + 4096 + ((ntg0 + nt) * 4 + s) * 2 * 32;
#pragma unroll
                for (int r = 0; r < 2; r++)
                    bfr[nt][r] = __float_as_uint(base[r * 32 + lane]);
            }
#pragma unroll
            for (int mt = 0; mt < 4; mt++)
#pragma unroll
                for (int nt = 0; nt < 8; nt++)
                    mma_tf32(acc[mt][nt], afr[mt], bfr[nt]);
        }
        __syncthreads();   // stage kt free for reuse at iter kt+1's issue
    }

    const int g = lane >> 2;
    const int tg = lane & 3;
#pragma unroll
    for (int mt = 0; mt < 4; mt++) {
#pragma unroll
        for (int rh = 0; rh < 2; rh++) {
            const int m = m0 + wm + mt * 16 + g + rh * 8;
#pragma unroll
            for (int nt = 0; nt < 8; nt++) {
                const int n = n0 + wn + nt * 8 + tg * 2;
                float v0 = acc[mt][nt][rh * 2 + 0];
                float v1 = acc[mt][nt][rh * 2 + 1];
                if (MODE == 0) {
                    const int bb = m >> 11, ss = m & 2047;
                    const int hh = n >> 6,  dd = n & 63;
                    float* dst = C + (((size_t)bb * NHEADS + hh) * SEQ + ss) * DHEAD + dd;
                    *(float2*)dst = make_float2(rna32(v0), rna32(v1));
                } else {
                    float* dst = C + (size_t)m * EMB + n;
                    *(float2*)dst = make_float2(v0 + bias[n], v1 + bias[n + 1]);
                }
            }
        }
    }
}

// ===========================================================================
// Tensor-core causal flash attention, MT=2 (32 Q rows / warp). Unchanged
// from round 5 (pre-rounded operands; truncation in LDS path is exact).
// ===========================================================================
#define KLD 68
#define VLD 72
#define PLD 68
#define K_OFF(p) ((p) * (64 * KLD))
#define V_OFF(p) (2 * 64 * KLD + (p) * (64 * VLD))
#define P_OFF(w) (2 * 64 * KLD + 2 * 64 * VLD + (w) * (32 * PLD))
#define ATTN_SMEM ((2 * 64 * KLD + 2 * 64 * VLD + 8 * 32 * PLD) * 4)

__device__ __forceinline__ void attn_load_tile(uint32_t smbase, int tid, int buf,
                                               const float* kb, const float* vb) {
    uint32_t kdst = smbase + K_OFF(buf) * 4;
    uint32_t vdst = smbase + V_OFF(buf) * 4;
#pragma unroll
    for (int it = 0; it < 4; it++) {
        int id = tid + it * 256;
        int r = id >> 4;
        int c4 = (id & 15) * 4;
        cp16(kdst + (r * KLD + c4) * 4, kb + r * DHEAD + c4);
        cp16(vdst + (r * VLD + c4) * 4, vb + r * DHEAD + c4);
    }
    CP_COMMIT();
}

__global__ __launch_bounds__(256) void attn_tc(const float* __restrict__ Q,
                                               const float* __restrict__ Kg,
                                               const float* __restrict__ Vg,
                                               float* __restrict__ ctx) {
    extern __shared__ float smf[];
    const uint32_t smbase = smem_u32(smf);
    const int tid  = threadIdx.x;
    const int wid  = tid >> 5;
    const int lane = tid & 31;
    const int g    = lane >> 2;
    const int tg   = lane & 3;
    const int blkE = gridDim.x - 1 - blockIdx.x;
    const int h = blockIdx.y;
    const int b = blockIdx.z;
    const int wrow = blkE * 256 + wid * 32;

    const float* qb  = Q  + (((size_t)b * NHEADS + h) * SEQ + wrow) * DHEAD;
    const float* kb0 = Kg + (((size_t)b * NHEADS + h) * SEQ) * DHEAD;
    const float* vb0 = Vg + (((size_t)b * NHEADS + h) * SEQ) * DHEAD;

    uint32_t qf[2][8][4];
#pragma unroll
    for (int mt = 0; mt < 2; mt++) {
        const float* qm = qb + (size_t)mt * 16 * DHEAD;
#pragma unroll
        for (int kk = 0; kk < 8; kk++) {
            qf[mt][kk][0] = __float_as_uint(0.125f * qm[(size_t)g * DHEAD + kk * 8 + tg]);
            qf[mt][kk][1] = __float_as_uint(0.125f * qm[(size_t)(g + 8) * DHEAD + kk * 8 + tg]);
            qf[mt][kk][2] = __float_as_uint(0.125f * qm[(size_t)g * DHEAD + kk * 8 + tg + 4]);
            qf[mt][kk][3] = __float_as_uint(0.125f * qm[(size_t)(g + 8) * DHEAD + kk * 8 + tg + 4]);
        }
    }

    float oacc[2][8][4];
#pragma unroll
    for (int mt = 0; mt < 2; mt++)
#pragma unroll
        for (int nt = 0; nt < 8; nt++)
#pragma unroll
            for (int r = 0; r < 4; r++) oacc[mt][nt][r] = 0.f;
    float m_[2][2] = {{-1e30f, -1e30f}, {-1e30f, -1e30f}};
    float l_[2][2] = {{0.f, 0.f}, {0.f, 0.f}};

    const int nT = 4 * blkE + 4;
    attn_load_tile(smbase, tid, 0, kb0, vb0);

    for (int jt = 0; jt < nT; jt++) {
        const int p = jt & 1;
        if (jt + 1 < nT) {
            attn_load_tile(smbase, tid, 1 - p,
                           kb0 + (size_t)(jt + 1) * 64 * DHEAD,
                           vb0 + (size_t)(jt + 1) * 64 * DHEAD);
            CP_WAIT(1);
        } else {
            CP_WAIT(0);
        }
        __syncthreads();

        if (jt * 64 <= wrow + 31) {
            const float* Ks = smf + K_OFF(p);
            const float* Vs = smf + V_OFF(p);
            float* Ps = smf + P_OFF(wid);

            float sacc[2][8][4];
#pragma unroll
            for (int mt = 0; mt < 2; mt++)
#pragma unroll
                for (int nt = 0; nt < 8; nt++)
#pragma unroll
                    for (int r = 0; r < 4; r++) sacc[mt][nt][r] = 0.f;

#pragma unroll
            for (int nt = 0; nt < 8; nt++) {
                const float* krow = Ks + (nt * 8 + g) * KLD;
#pragma unroll
                for (int kk = 0; kk < 8; kk++) {
                    uint32_t bb[2];
                    bb[0] = __float_as_uint(krow[kk * 8 + tg]);
                    bb[1] = __float_as_uint(krow[kk * 8 + tg + 4]);
                    mma_tf32(sacc[0][nt], qf[0][kk], bb);
                    mma_tf32(sacc[1][nt], qf[1][kk], bb);
                }
            }

            if (jt * 64 + 63 > wrow) {
#pragma unroll
                for (int mt = 0; mt < 2; mt++) {
#pragma unroll
                    for (int nt = 0; nt < 8; nt++) {
                        int colb = jt * 64 + nt * 8 + 2 * tg;
#pragma unroll
                        for (int rh = 0; rh < 2; rh++) {
                            int row = wrow + mt * 16 + g + 8 * rh;
                            if (colb > row)     sacc[mt][nt][rh * 2 + 0] = -1e30f;
                            if (colb + 1 > row) sacc[mt][nt][rh * 2 + 1] = -1e30f;
                        }
                    }
                }
            }

#pragma unroll
            for (int mt = 0; mt < 2; mt++) {
                float rmax[2] = {-1e30f, -1e30f};
#pragma unroll
                for (int nt = 0; nt < 8; nt++)
#pragma unroll
                    for (int rh = 0; rh < 2; rh++)
                        rmax[rh] = fmaxf(rmax[rh],
                                         fmaxf(sacc[mt][nt][rh * 2], sacc[mt][nt][rh * 2 + 1]));
#pragma unroll
                for (int rh = 0; rh < 2; rh++) {
                    rmax[rh] = fmaxf(rmax[rh], __shfl_xor_sync(0xffffffffu, rmax[rh], 1));
                    rmax[rh] = fmaxf(rmax[rh], __shfl_xor_sync(0xffffffffu, rmax[rh], 2));
                }
                float alpha[2], rsum[2] = {0.f, 0.f};
#pragma unroll
                for (int rh = 0; rh < 2; rh++) {
                    float mnew = fmaxf(m_[mt][rh], rmax[rh]);
                    alpha[rh] = __expf(m_[mt][rh] - mnew);
                    m_[mt][rh] = mnew;
                }
#pragma unroll
                for (int nt = 0; nt < 8; nt++)
#pragma unroll
                    for (int rh = 0; rh < 2; rh++) {
                        float p0 = __expf(sacc[mt][nt][rh * 2 + 0] - m_[mt][rh]);
                        float p1 = __expf(sacc[mt][nt][rh * 2 + 1] - m_[mt][rh]);
                        sacc[mt][nt][rh * 2 + 0] = p0;
                        sacc[mt][nt][rh * 2 + 1] = p1;
                        rsum[rh] += p0 + p1;
                    }
#pragma unroll
                for (int rh = 0; rh < 2; rh++) {
                    rsum[rh] += __shfl_xor_sync(0xffffffffu, rsum[rh], 1);
                    rsum[rh] += __shfl_xor_sync(0xffffffffu, rsum[rh], 2);
                    l_[mt][rh] = l_[mt][rh] * alpha[rh] + rsum[rh];
                }
#pragma unroll
                for (int nt = 0; nt < 8; nt++)
#pragma unroll
                    for (int rh = 0; rh < 2; rh++) {
                        oacc[mt][nt][rh * 2 + 0] *= alpha[rh];
                        oacc[mt][nt][rh * 2 + 1] *= alpha[rh];
                    }
            }

#pragma unroll
            for (int mt = 0; mt < 2; mt++)
#pragma unroll
                for (int nt = 0; nt < 8; nt++) {
                    uint2 u0 = make_uint2(f2tf32(sacc[mt][nt][0]), f2tf32(sacc[mt][nt][1]));
                    uint2 u1 = make_uint2(f2tf32(sacc[mt][nt][2]), f2tf32(sacc[mt][nt][3]));
                    *(uint2*)&Ps[(mt * 16 + g) * PLD + nt * 8 + 2 * tg] = u0;
                    *(uint2*)&Ps[(mt * 16 + g + 8) * PLD + nt * 8 + 2 * tg] = u1;
                }
            __syncwarp();

#pragma unroll
            for (int kkc = 0; kkc < 8; kkc++) {
                uint32_t a[2][4];
#pragma unroll
                for (int mt = 0; mt < 2; mt++) {
                    a[mt][0] = __float_as_uint(Ps[(mt * 16 + g) * PLD + kkc * 8 + tg]);
                    a[mt][1] = __float_as_uint(Ps[(mt * 16 + g + 8) * PLD + kkc * 8 + tg]);
                    a[mt][2] = __float_as_uint(Ps[(mt * 16 + g) * PLD + kkc * 8 + tg + 4]);
                    a[mt][3] = __float_as_uint(Ps[(mt * 16 + g + 8) * PLD + kkc * 8 + tg + 4]);
                }
                const float* v0 = Vs + (kkc * 8 + tg) * VLD;
                const float* v1 = Vs + (kkc * 8 + tg + 4) * VLD;
#pragma unroll
                for (int ntd = 0; ntd < 8; ntd++) {
                    uint32_t bb[2];
                    bb[0] = __float_as_uint(v0[ntd * 8 + g]);
                    bb[1] = __float_as_uint(v1[ntd * 8 + g]);
                    mma_tf32(oacc[0][ntd], a[0], bb);
                    mma_tf32(oacc[1][ntd], a[1], bb);
                }
            }
        }
        __syncthreads();
    }

#pragma unroll
    for (int mt = 0; mt < 2; mt++) {
        float inv[2] = {1.f / l_[mt][0], 1.f / l_[mt][1]};
#pragma unroll
        for (int rh = 0; rh < 2; rh++) {
            const int r = wrow + mt * 16 + g + 8 * rh;
            float* dst = ctx + ((size_t)b * SEQ + r) * EMB + h * DHEAD + 2 * tg;
#pragma unroll
            for (int nt = 0; nt < 8; nt++) {
                float2 v = make_float2(rna32(oacc[mt][nt][rh * 2 + 0] * inv[rh]),
                                       rna32(oacc[mt][nt][rh * 2 + 1] * inv[rh]));
                *(float2*)(dst + nt * 8) = v;
            }
        }
    }
}

// ---------------------------------------------------------------------------
extern "C" void kernel_launch(void* const* d_in, const int* in_sizes, int n_in,
                              void* d_out, int out_size) {
    const float* x  = (const float*)d_in[0];
    const float* Wk = (const float*)d_in[1];
    const float* Wq = (const float*)d_in[2];
    const float* Wv = (const float*)d_in[3];
    const float* Wu = (const float*)d_in[4];
    const float* bu = (const float*)d_in[5];
    float* out = (float*)d_out;

    float *qp, *kp, *vp, *cp, *xr, *wk, *wq, *wv, *wu;
    cudaGetSymbolAddress((void**)&qp, g_q);
    cudaGetSymbolAddress((void**)&kp, g_k);
    cudaGetSymbolAddress((void**)&vp, g_v);
    cudaGetSymbolAddress((void**)&cp, g_ctx);
    cudaGetSymbolAddress((void**)&xr, g_xr);
    cudaGetSymbolAddress((void**)&wk, g_wk);
    cudaGetSymbolAddress((void**)&wq, g_wq);
    cudaGetSymbolAddress((void**)&wv, g_wv);
    cudaGetSymbolAddress((void**)&wu, g_wu);

    cudaFuncSetAttribute(gemm_tc<0>, cudaFuncAttributeMaxDynamicSharedMemorySize, GEMM_SMEM);
    cudaFuncSetAttribute(gemm_tc<1>, cudaFuncAttributeMaxDynamicSharedMemorySize, GEMM_SMEM);
    cudaFuncSetAttribute(attn_tc, cudaFuncAttributeMaxDynamicSharedMemorySize, ATTN_SMEM);

    preround<<<8192, 256>>>((const float4*)x, (const float4*)Wk, (const float4*)Wq,
                            (const float4*)Wv, (const float4*)Wu);

    dim3 gg(EMB / 128, (NBATCH * SEQ) / 128);  // (8, 32)
    gemm_tc<0><<<gg, 128, GEMM_SMEM>>>(xr, wq, qp, nullptr);
    gemm_tc<0><<<gg, 128, GEMM_SMEM>>>(xr, wk, kp, nullptr);
    gemm_tc<0><<<gg, 128, GEMM_SMEM>>>(xr, wv, vp, nullptr);

    attn_tc<<<dim3(SEQ / 256, NHEADS, NBATCH), 256, ATTN_SMEM>>>(qp, kp, vp, cp);

    gemm_tc<1><<<gg, 128, GEMM_SMEM>>>(cp, wu, out, bu);
}

// round 7
// speedup vs baseline: 1.0183x; 1.0143x over previous
#include <cuda_runtime.h>
#include <cstdint>
#include <math.h>

#define NHEADS 16
#define SEQ    2048
#define EMB    1024
#define NBATCH 2
#define DHEAD  64

// Scratch (allocation-free rule): device globals.
__device__ float g_q[NBATCH * NHEADS * SEQ * DHEAD];
__device__ float g_k[NBATCH * NHEADS * SEQ * DHEAD];
__device__ float g_v[NBATCH * NHEADS * SEQ * DHEAD];
__device__ float g_ctx[NBATCH * SEQ * EMB];
// Pre-rounded (tf32-grid) copies of inputs.
__device__ float g_xr[NBATCH * SEQ * EMB];
__device__ float g_wk[EMB * EMB];
__device__ float g_wq[EMB * EMB];
__device__ float g_wv[EMB * EMB];
__device__ float g_wu[EMB * EMB];

// ===========================================================================
// helpers
// ===========================================================================
__device__ __forceinline__ uint32_t f2tf32(float f) {
    uint32_t u;
    asm("cvt.rna.tf32.f32 %0, %1;" : "=r"(u) : "f"(f));
    return u;
}
__device__ __forceinline__ float rna32(float f) { return __uint_as_float(f2tf32(f)); }
__device__ __forceinline__ void mma_tf32(float c[4], const uint32_t a[4], const uint32_t b[2]) {
    asm volatile(
        "mma.sync.aligned.m16n8k8.row.col.f32.tf32.tf32.f32 "
        "{%0,%1,%2,%3}, {%4,%5,%6,%7}, {%8,%9}, {%0,%1,%2,%3};"
        : "+f"(c[0]), "+f"(c[1]), "+f"(c[2]), "+f"(c[3])
        : "r"(a[0]), "r"(a[1]), "r"(a[2]), "r"(a[3]), "r"(b[0]), "r"(b[1]));
}
__device__ __forceinline__ void cp16(uint32_t saddr, const void* gptr) {
    asm volatile("cp.async.cg.shared.global [%0], [%1], 16;" :: "r"(saddr), "l"(gptr));
}
#define CP_COMMIT() asm volatile("cp.async.commit_group;" ::: "memory")
#define CP_WAIT(n)  asm volatile("cp.async.wait_group %0;" :: "n"(n) : "memory")
__device__ __forceinline__ uint32_t smem_u32(const void* p) {
    uint32_t a;
    asm("{ .reg .u64 t; cvta.to.shared.u64 t, %1; cvt.u32.u64 %0, t; }" : "=r"(a) : "l"(p));
    return a;
}

// ===========================================================================
// Pre-round inputs to tf32 grid (RNA).
// ===========================================================================
__global__ __launch_bounds__(256) void preround(const float4* __restrict__ x,
                                                const float4* __restrict__ wk,
                                                const float4* __restrict__ wq,
                                                const float4* __restrict__ wv,
                                                const float4* __restrict__ wu) {
    int i = blockIdx.x * 256 + threadIdx.x;
    const float4* src;
    float4* dst;
    if (i < 1048576) {
        src = x + i;
        dst = (float4*)g_xr + i;
    } else {
        int j = i - 1048576;
        int w = j >> 18;
        int l = j & 262143;
        if (w == 0)      { src = wk + l; dst = (float4*)g_wk + l; }
        else if (w == 1) { src = wq + l; dst = (float4*)g_wq + l; }
        else if (w == 2) { src = wv + l; dst = (float4*)g_wv + l; }
        else             { src = wu + l; dst = (float4*)g_wu + l; }
    }
    float4 v = *src;
    *dst = make_float4(rna32(v.x), rna32(v.y), rna32(v.z), rna32(v.w));
}

// ===========================================================================
// Tensor-core NT GEMM: C[m,n] = sum_k A[m,k]*B[n,k].  M=4096, N=1024, K=1024.
// 256 threads, 8 warps (warp tile 64x32) -> ~110 regs -> 2 CTAs/SM resident.
// 3-stage cp.async pipeline, issue-before-wait, 2 groups in flight.
// MODE 0: fused QKV — blockIdx.z selects weight + [B,H,S,D] destination.
// MODE 1: row-major + bias.
// ===========================================================================
#define GK          1024
#define KT          32
#define NKT         (GK / KT)
#define STAGE_FLT   8192
#define STAGE_BYTES (STAGE_FLT * 4)
#define NSTAGE      3
#define GEMM_SMEM   (NSTAGE * STAGE_BYTES)   // 98304

__device__ __forceinline__ void gemm_issue(uint32_t smb, int kt,
                                           const float* Ap0, const float* Bp0,
                                           const int offA[4], const int offB[4]) {
    uint32_t base = smb + (kt % NSTAGE) * STAGE_BYTES;
    const float* Ap = Ap0 + kt * KT;
    const float* Bp = Bp0 + kt * KT;
#pragma unroll
    for (int j = 0; j < 4; j++) {
        cp16(base + offA[j] * 4, Ap + j * 4);
        cp16(base + offB[j] * 4, Bp + j * 4);
    }
}

template <int MODE>
__global__ __launch_bounds__(256) void gemm_tc(const float* __restrict__ A,
                                               const float* __restrict__ B0,
                                               const float* __restrict__ B1,
                                               const float* __restrict__ B2,
                                               float* __restrict__ C0,
                                               float* __restrict__ C1,
                                               float* __restrict__ C2,
                                               const float* __restrict__ bias) {
    extern __shared__ float smf[];
    const uint32_t smb = smem_u32(smf);
    const int tid = threadIdx.x;
    const int wid = tid >> 5;
    const int lane = tid & 31;
    const int m0 = blockIdx.y * 128;
    const int n0 = blockIdx.x * 128;
    const int wm = (wid >> 2) * 64;
    const int wn = (wid & 3) * 32;
    const int z = blockIdx.z;
    const float* Bm = (z == 0) ? B0 : (z == 1) ? B1 : B2;
    float* C = (z == 0) ? C0 : (z == 1) ? C1 : C2;

    const int lr = tid >> 1;
    const int lkb = (tid & 1) * 16;
    const float* Ap0 = A  + (size_t)(m0 + lr) * GK + lkb;
    const float* Bp0 = Bm + (size_t)(n0 + lr) * GK + lkb;

    int offA[4], offB[4];
#pragma unroll
    for (int j = 0; j < 4; j++) {
        int k = lkb + j * 4;
        int s = k >> 3;
        int half = (k >> 2) & 1;
        {
            int mt = lr >> 4, rr = lr & 15, g = rr & 7;
            int reg = (rr >> 3) + half * 2;
            offA[j] = ((mt * 4 + s) * 4 + reg) * 32 + g * 4;
        }
        {
            int nt = lr >> 3, g = lr & 7;
            offB[j] = 4096 + ((nt * 4 + s) * 2 + half) * 32 + g * 4;
        }
    }

    float acc[4][4][4];
#pragma unroll
    for (int i = 0; i < 4; i++)
#pragma unroll
        for (int j = 0; j < 4; j++)
#pragma unroll
            for (int r = 0; r < 4; r++) acc[i][j][r] = 0.f;

    gemm_issue(smb, 0, Ap0, Bp0, offA, offB);
    CP_COMMIT();
    gemm_issue(smb, 1, Ap0, Bp0, offA, offB);
    CP_COMMIT();

    const int mtg0 = wm >> 4;
    const int ntg0 = wn >> 3;

    for (int kt = 0; kt < NKT; kt++) {
        if (kt + 2 < NKT) gemm_issue(smb, kt + 2, Ap0, Bp0, offA, offB);
        CP_COMMIT();
        CP_WAIT(2);
        __syncthreads();

        const float* buf = smf + (kt % NSTAGE) * STAGE_FLT;
#pragma unroll
        for (int s = 0; s < 4; s++) {
            uint32_t afr[4][4], bfr[4][2];
#pragma unroll
            for (int mt = 0; mt < 4; mt++) {
                const float* base = buf + ((mtg0 + mt) * 4 + s) * 4 * 32;
#pragma unroll
                for (int r = 0; r < 4; r++)
                    afr[mt][r] = __float_as_uint(base[r * 32 + lane]);
            }
#pragma unroll
            for (int nt = 0; nt < 4; nt++) {
                const float* base = buf + 4096 + ((ntg0 + nt) * 4 + s) * 2 * 32;
#pragma unroll
                for (int r = 0; r < 2; r++)
                    bfr[nt][r] = __float_as_uint(base[r * 32 + lane]);
            }
#pragma unroll
            for (int mt = 0; mt < 4; mt++)
#pragma unroll
                for (int nt = 0; nt < 4; nt++)
                    mma_tf32(acc[mt][nt], afr[mt], bfr[nt]);
        }
        __syncthreads();
    }

    const int g = lane >> 2;
    const int tg = lane & 3;
#pragma unroll
    for (int mt = 0; mt < 4; mt++) {
#pragma unroll
        for (int rh = 0; rh < 2; rh++) {
            const int m = m0 + wm + mt * 16 + g + rh * 8;
#pragma unroll
            for (int nt = 0; nt < 4; nt++) {
                const int n = n0 + wn + nt * 8 + tg * 2;
                float v0 = acc[mt][nt][rh * 2 + 0];
                float v1 = acc[mt][nt][rh * 2 + 1];
                if (MODE == 0) {
                    const int bb = m >> 11, ss = m & 2047;
                    const int hh = n >> 6,  dd = n & 63;
                    float* dst = C + (((size_t)bb * NHEADS + hh) * SEQ + ss) * DHEAD + dd;
                    *(float2*)dst = make_float2(rna32(v0), rna32(v1));
                } else {
                    float* dst = C + (size_t)m * EMB + n;
                    *(float2*)dst = make_float2(v0 + bias[n], v1 + bias[n + 1]);
                }
            }
        }
    }
}

// ===========================================================================
// Tensor-core causal flash attention, MT=2 (32 Q rows / warp). Unchanged.
// ===========================================================================
#define KLD 68
#define VLD 72
#define PLD 68
#define K_OFF(p) ((p) * (64 * KLD))
#define V_OFF(p) (2 * 64 * KLD + (p) * (64 * VLD))
#define P_OFF(w) (2 * 64 * KLD + 2 * 64 * VLD + (w) * (32 * PLD))
#define ATTN_SMEM ((2 * 64 * KLD + 2 * 64 * VLD + 8 * 32 * PLD) * 4)

__device__ __forceinline__ void attn_load_tile(uint32_t smbase, int tid, int buf,
                                               const float* kb, const float* vb) {
    uint32_t kdst = smbase + K_OFF(buf) * 4;
    uint32_t vdst = smbase + V_OFF(buf) * 4;
#pragma unroll
    for (int it = 0; it < 4; it++) {
        int id = tid + it * 256;
        int r = id >> 4;
        int c4 = (id & 15) * 4;
        cp16(kdst + (r * KLD + c4) * 4, kb + r * DHEAD + c4);
        cp16(vdst + (r * VLD + c4) * 4, vb + r * DHEAD + c4);
    }
    CP_COMMIT();
}

__global__ __launch_bounds__(256) void attn_tc(const float* __restrict__ Q,
                                               const float* __restrict__ Kg,
                                               const float* __restrict__ Vg,
                                               float* __restrict__ ctx) {
    extern __shared__ float smf[];
    const uint32_t smbase = smem_u32(smf);
    const int tid  = threadIdx.x;
    const int wid  = tid >> 5;
    const int lane = tid & 31;
    const int g    = lane >> 2;
    const int tg   = lane & 3;
    const int blkE = gridDim.x - 1 - blockIdx.x;
    const int h = blockIdx.y;
    const int b = blockIdx.z;
    const int wrow = blkE * 256 + wid * 32;

    const float* qb  = Q  + (((size_t)b * NHEADS + h) * SEQ + wrow) * DHEAD;
    const float* kb0 = Kg + (((size_t)b * NHEADS + h) * SEQ) * DHEAD;
    const float* vb0 = Vg + (((size_t)b * NHEADS + h) * SEQ) * DHEAD;

    uint32_t qf[2][8][4];
#pragma unroll
    for (int mt = 0; mt < 2; mt++) {
        const float* qm = qb + (size_t)mt * 16 * DHEAD;
#pragma unroll
        for (int kk = 0; kk < 8; kk++) {
            qf[mt][kk][0] = __float_as_uint(0.125f * qm[(size_t)g * DHEAD + kk * 8 + tg]);
            qf[mt][kk][1] = __float_as_uint(0.125f * qm[(size_t)(g + 8) * DHEAD + kk * 8 + tg]);
            qf[mt][kk][2] = __float_as_uint(0.125f * qm[(size_t)g * DHEAD + kk * 8 + tg + 4]);
            qf[mt][kk][3] = __float_as_uint(0.125f * qm[(size_t)(g + 8) * DHEAD + kk * 8 + tg + 4]);
        }
    }

    float oacc[2][8][4];
#pragma unroll
    for (int mt = 0; mt < 2; mt++)
#pragma unroll
        for (int nt = 0; nt < 8; nt++)
#pragma unroll
            for (int r = 0; r < 4; r++) oacc[mt][nt][r] = 0.f;
    float m_[2][2] = {{-1e30f, -1e30f}, {-1e30f, -1e30f}};
    float l_[2][2] = {{0.f, 0.f}, {0.f, 0.f}};

    const int nT = 4 * blkE + 4;
    attn_load_tile(smbase, tid, 0, kb0, vb0);

    for (int jt = 0; jt < nT; jt++) {
        const int p = jt & 1;
        if (jt + 1 < nT) {
            attn_load_tile(smbase, tid, 1 - p,
                           kb0 + (size_t)(jt + 1) * 64 * DHEAD,
                           vb0 + (size_t)(jt + 1) * 64 * DHEAD);
            CP_WAIT(1);
        } else {
            CP_WAIT(0);
        }
        __syncthreads();

        if (jt * 64 <= wrow + 31) {
            const float* Ks = smf + K_OFF(p);
            const float* Vs = smf + V_OFF(p);
            float* Ps = smf + P_OFF(wid);

            float sacc[2][8][4];
#pragma unroll
            for (int mt = 0; mt < 2; mt++)
#pragma unroll
                for (int nt = 0; nt < 8; nt++)
#pragma unroll
                    for (int r = 0; r < 4; r++) sacc[mt][nt][r] = 0.f;

#pragma unroll
            for (int nt = 0; nt < 8; nt++) {
                const float* krow = Ks + (nt * 8 + g) * KLD;
#pragma unroll
                for (int kk = 0; kk < 8; kk++) {
                    uint32_t bb[2];
                    bb[0] = __float_as_uint(krow[kk * 8 + tg]);
                    bb[1] = __float_as_uint(krow[kk * 8 + tg + 4]);
                    mma_tf32(sacc[0][nt], qf[0][kk], bb);
                    mma_tf32(sacc[1][nt], qf[1][kk], bb);
                }
            }

            if (jt * 64 + 63 > wrow) {
#pragma unroll
                for (int mt = 0; mt < 2; mt++) {
#pragma unroll
                    for (int nt = 0; nt < 8; nt++) {
                        int colb = jt * 64 + nt * 8 + 2 * tg;
#pragma unroll
                        for (int rh = 0; rh < 2; rh++) {
                            int row = wrow + mt * 16 + g + 8 * rh;
                            if (colb > row)     sacc[mt][nt][rh * 2 + 0] = -1e30f;
                            if (colb + 1 > row) sacc[mt][nt][rh * 2 + 1] = -1e30f;
                        }
                    }
                }
            }

#pragma unroll
            for (int mt = 0; mt < 2; mt++) {
                float rmax[2] = {-1e30f, -1e30f};
#pragma unroll
                for (int nt = 0; nt < 8; nt++)
#pragma unroll
                    for (int rh = 0; rh < 2; rh++)
                        rmax[rh] = fmaxf(rmax[rh],
                                         fmaxf(sacc[mt][nt][rh * 2], sacc[mt][nt][rh * 2 + 1]));
#pragma unroll
                for (int rh = 0; rh < 2; rh++) {
                    rmax[rh] = fmaxf(rmax[rh], __shfl_xor_sync(0xffffffffu, rmax[rh], 1));
                    rmax[rh] = fmaxf(rmax[rh], __shfl_xor_sync(0xffffffffu, rmax[rh], 2));
                }
                float alpha[2], rsum[2] = {0.f, 0.f};
#pragma unroll
                for (int rh = 0; rh < 2; rh++) {
                    float mnew = fmaxf(m_[mt][rh], rmax[rh]);
                    alpha[rh] = __expf(m_[mt][rh] - mnew);
                    m_[mt][rh] = mnew;
                }
#pragma unroll
                for (int nt = 0; nt < 8; nt++)
#pragma unroll
                    for (int rh = 0; rh < 2; rh++) {
                        float p0 = __expf(sacc[mt][nt][rh * 2 + 0] - m_[mt][rh]);
                        float p1 = __expf(sacc[mt][nt][rh * 2 + 1] - m_[mt][rh]);
                        sacc[mt][nt][rh * 2 + 0] = p0;
                        sacc[mt][nt][rh * 2 + 1] = p1;
                        rsum[rh] += p0 + p1;
                    }
#pragma unroll
                for (int rh = 0; rh < 2; rh++) {
                    rsum[rh] += __shfl_xor_sync(0xffffffffu, rsum[rh], 1);
                    rsum[rh] += __shfl_xor_sync(0xffffffffu, rsum[rh], 2);
                    l_[mt][rh] = l_[mt][rh] * alpha[rh] + rsum[rh];
                }
#pragma unroll
                for (int nt = 0; nt < 8; nt++)
#pragma unroll
                    for (int rh = 0; rh < 2; rh++) {
                        oacc[mt][nt][rh * 2 + 0] *= alpha[rh];
                        oacc[mt][nt][rh * 2 + 1] *= alpha[rh];
                    }
            }

#pragma unroll
            for (int mt = 0; mt < 2; mt++)
#pragma unroll
                for (int nt = 0; nt < 8; nt++) {
                    uint2 u0 = make_uint2(f2tf32(sacc[mt][nt][0]), f2tf32(sacc[mt][nt][1]));
                    uint2 u1 = make_uint2(f2tf32(sacc[mt][nt][2]), f2tf32(sacc[mt][nt][3]));
                    *(uint2*)&Ps[(mt * 16 + g) * PLD + nt * 8 + 2 * tg] = u0;
                    *(uint2*)&Ps[(mt * 16 + g + 8) * PLD + nt * 8 + 2 * tg] = u1;
                }
            __syncwarp();

#pragma unroll
            for (int kkc = 0; kkc < 8; kkc++) {
                uint32_t a[2][4];
#pragma unroll
                for (int mt = 0; mt < 2; mt++) {
                    a[mt][0] = __float_as_uint(Ps[(mt * 16 + g) * PLD + kkc * 8 + tg]);
                    a[mt][1] = __float_as_uint(Ps[(mt * 16 + g + 8) * PLD + kkc * 8 + tg]);
                    a[mt][2] = __float_as_uint(Ps[(mt * 16 + g) * PLD + kkc * 8 + tg + 4]);
                    a[mt][3] = __float_as_uint(Ps[(mt * 16 + g + 8) * PLD + kkc * 8 + tg + 4]);
                }
                const float* v0 = Vs + (kkc * 8 + tg) * VLD;
                const float* v1 = Vs + (kkc * 8 + tg + 4) * VLD;
#pragma unroll
                for (int ntd = 0; ntd < 8; ntd++) {
                    uint32_t bb[2];
                    bb[0] = __float_as_uint(v0[ntd * 8 + g]);
                    bb[1] = __float_as_uint(v1[ntd * 8 + g]);
                    mma_tf32(oacc[0][ntd], a[0], bb);
                    mma_tf32(oacc[1][ntd], a[1], bb);
                }
            }
        }
        __syncthreads();
    }

#pragma unroll
    for (int mt = 0; mt < 2; mt++) {
        float inv[2] = {1.f / l_[mt][0], 1.f / l_[mt][1]};
#pragma unroll
        for (int rh = 0; rh < 2; rh++) {
            const int r = wrow + mt * 16 + g + 8 * rh;
            float* dst = ctx + ((size_t)b * SEQ + r) * EMB + h * DHEAD + 2 * tg;
#pragma unroll
            for (int nt = 0; nt < 8; nt++) {
                float2 v = make_float2(rna32(oacc[mt][nt][rh * 2 + 0] * inv[rh]),
                                       rna32(oacc[mt][nt][rh * 2 + 1] * inv[rh]));
                *(float2*)(dst + nt * 8) = v;
            }
        }
    }
}

// ---------------------------------------------------------------------------
extern "C" void kernel_launch(void* const* d_in, const int* in_sizes, int n_in,
                              void* d_out, int out_size) {
    const float* x  = (const float*)d_in[0];
    const float* Wk = (const float*)d_in[1];
    const float* Wq = (const float*)d_in[2];
    const float* Wv = (const float*)d_in[3];
    const float* Wu = (const float*)d_in[4];
    const float* bu = (const float*)d_in[5];
    float* out = (float*)d_out;

    float *qp, *kp, *vp, *cp, *xr, *wk, *wq, *wv, *wu;
    cudaGetSymbolAddress((void**)&qp, g_q);
    cudaGetSymbolAddress((void**)&kp, g_k);
    cudaGetSymbolAddress((void**)&vp, g_v);
    cudaGetSymbolAddress((void**)&cp, g_ctx);
    cudaGetSymbolAddress((void**)&xr, g_xr);
    cudaGetSymbolAddress((void**)&wk, g_wk);
    cudaGetSymbolAddress((void**)&wq, g_wq);
    cudaGetSymbolAddress((void**)&wv, g_wv);
    cudaGetSymbolAddress((void**)&wu, g_wu);

    cudaFuncSetAttribute(gemm_tc<0>, cudaFuncAttributeMaxDynamicSharedMemorySize, GEMM_SMEM);
    cudaFuncSetAttribute(gemm_tc<1>, cudaFuncAttributeMaxDynamicSharedMemorySize, GEMM_SMEM);
    cudaFuncSetAttribute(attn_tc, cudaFuncAttributeMaxDynamicSharedMemorySize, ATTN_SMEM);

    preround<<<8192, 256>>>((const float4*)x, (const float4*)Wk, (const float4*)Wq,
                            (const float4*)Wv, (const float4*)Wu);

    // Fused Q/K/V projection: z selects weight + destination.
    dim3 gqkv(EMB / 128, (NBATCH * SEQ) / 128, 3);
    gemm_tc<0><<<gqkv, 256, GEMM_SMEM>>>(xr, wq, wk, wv, qp, kp, vp, nullptr);

    attn_tc<<<dim3(SEQ / 256, NHEADS, NBATCH), 256, ATTN_SMEM>>>(qp, kp, vp, cp);

    dim3 go(EMB / 128, (NBATCH * SEQ) / 128, 1);
    gemm_tc<1><<<go, 256, GEMM_SMEM>>>(cp, wu, nullptr, nullptr, out, nullptr, nullptr, bu);
}

// round 8
// speedup vs baseline: 1.8104x; 1.7779x over previous
#include <cuda_runtime.h>
#include <cuda_fp16.h>
#include <cstdint>
#include <math.h>

#define NHEADS 16
#define SEQ    2048
#define EMB    1024
#define NBATCH 2
#define DHEAD  64

// Scratch (allocation-free rule): device globals. All fp16.
__device__ __half g_q[NBATCH * NHEADS * SEQ * DHEAD];     // [B,H,S,D]
__device__ __half g_k[NBATCH * NHEADS * SEQ * DHEAD];     // [B,H,S,D]
__device__ __half g_v[NBATCH * NHEADS * SEQ * DHEAD];     // [B,H,D,S]  (transposed!)
__device__ __half g_ctx[NBATCH * SEQ * EMB];              // [B,S,E]
__device__ __half g_xh[NBATCH * SEQ * EMB];
__device__ __half g_wk[EMB * EMB];
__device__ __half g_wq[EMB * EMB];
__device__ __half g_wv[EMB * EMB];
__device__ __half g_wu[EMB * EMB];

// ===========================================================================
// helpers
// ===========================================================================
__device__ __forceinline__ void mma_f16(float c[4], const uint32_t a[4], const uint32_t b[2]) {
    asm volatile(
        "mma.sync.aligned.m16n8k16.row.col.f32.f16.f16.f32 "
        "{%0,%1,%2,%3}, {%4,%5,%6,%7}, {%8,%9}, {%0,%1,%2,%3};"
        : "+f"(c[0]), "+f"(c[1]), "+f"(c[2]), "+f"(c[3])
        : "r"(a[0]), "r"(a[1]), "r"(a[2]), "r"(a[3]), "r"(b[0]), "r"(b[1]));
}
__device__ __forceinline__ uint32_t pack2(float lo, float hi) {
    __half2 h = __floats2half2_rn(lo, hi);
    return *(uint32_t*)&h;
}
__device__ __forceinline__ void cp16(uint32_t saddr, const void* gptr) {
    asm volatile("cp.async.cg.shared.global [%0], [%1], 16;" :: "r"(saddr), "l"(gptr));
}
#define CP_COMMIT() asm volatile("cp.async.commit_group;" ::: "memory")
#define CP_WAIT(n)  asm volatile("cp.async.wait_group %0;" :: "n"(n) : "memory")
__device__ __forceinline__ uint32_t smem_u32(const void* p) {
    uint32_t a;
    asm("{ .reg .u64 t; cvta.to.shared.u64 t, %1; cvt.u32.u64 %0, t; }" : "=r"(a) : "l"(p));
    return a;
}

// ===========================================================================
// Pre-round inputs to fp16 (RNE). 2M float4 total: 1M x, 4 x 256K weights.
// ===========================================================================
__global__ __launch_bounds__(256) void preround(const float4* __restrict__ x,
                                                const float4* __restrict__ wk,
                                                const float4* __restrict__ wq,
                                                const float4* __restrict__ wv,
                                                const float4* __restrict__ wu) {
    int i = blockIdx.x * 256 + threadIdx.x;
    const float4* src;
    __half2* dst;
    if (i < 1048576) {
        src = x + i;
        dst = (__half2*)g_xh + i * 2;
    } else {
        int j = i - 1048576;
        int w = j >> 18;
        int l = j & 262143;
        if (w == 0)      { src = wk + l; dst = (__half2*)g_wk + l * 2; }
        else if (w == 1) { src = wq + l; dst = (__half2*)g_wq + l * 2; }
        else if (w == 2) { src = wv + l; dst = (__half2*)g_wv + l * 2; }
        else             { src = wu + l; dst = (__half2*)g_wu + l * 2; }
    }
    float4 v = *src;
    dst[0] = __floats2half2_rn(v.x, v.y);
    dst[1] = __floats2half2_rn(v.z, v.w);
}

// ===========================================================================
// fp16 tensor-core NT GEMM: C[m,n] = sum_k A[m,k]*B[n,k]. M=4096,N=1024,K=1024.
// m16n8k16 fragments cp.async'd DIRECTLY into frag layout.
//   A chunk (row r, k16-step s): 32B = [k0..7 -> reg (rr>>3)] [k8..15 -> reg+2]
//   B chunk (row n, s): 32B = [k0..7 -> b0] [k8..15 -> b1]
// K-chunk 64 (4 s-steps), 16 iters, 3-stage pipeline, 2 groups in flight.
// 256 thr, 8 warps, warp tile 64x32.
// MODE 0: z selects Wq/Wk/Wv; Q,K -> [B,H,S,D]; V -> [B,H,D,S] transposed.
// MODE 1: row-major fp32 + bias.
// ===========================================================================
#define GK          1024
#define KT          64
#define NKT         (GK / KT)
#define STAGE_BYTES 32768
#define B_REG_OFF   16384
#define NSTAGE      3
#define GEMM_SMEM   (NSTAGE * STAGE_BYTES)   // 98304

struct GemmLd {
    int offA[2][2], offB[2][2];   // [js][half] smem byte offsets (stage-rel)
    int gA[2][2], gB[2][2];       // gmem half-elem offsets (row-rel, chunk-rel)
};

__device__ __forceinline__ void gemm_issue(uint32_t smb, int kt, const GemmLd& L,
                                           const __half* ApR, const __half* BpR) {
    uint32_t base = smb + (kt % NSTAGE) * STAGE_BYTES;
    const __half* Ap = ApR + kt * KT;
    const __half* Bp = BpR + kt * KT;
#pragma unroll
    for (int js = 0; js < 2; js++)
#pragma unroll
        for (int hf = 0; hf < 2; hf++) {
            cp16(base + L.offA[js][hf], Ap + L.gA[js][hf]);
            cp16(base + L.offB[js][hf], Bp + L.gB[js][hf]);
        }
}

template <int MODE>
__global__ __launch_bounds__(256) void gemm_tc(const __half* __restrict__ A,
                                               const __half* __restrict__ B0,
                                               const __half* __restrict__ B1,
                                               const __half* __restrict__ B2,
                                               __half* __restrict__ C0,
                                               __half* __restrict__ C1,
                                               __half* __restrict__ C2,
                                               float* __restrict__ Cf,
                                               const float* __restrict__ bias) {
    extern __shared__ char sma[];
    const uint32_t smb = smem_u32(sma);
    const int tid = threadIdx.x;
    const int wid = tid >> 5;
    const int lane = tid & 31;
    const int m0 = blockIdx.y * 128;
    const int n0 = blockIdx.x * 128;
    const int wm = (wid >> 2) * 64;
    const int wn = (wid & 3) * 32;
    const int z = blockIdx.z;
    const __half* Bm = (MODE == 1) ? B0 : ((z == 0) ? B0 : (z == 1) ? B1 : B2);

    // loader: thread t -> row r = t>>1 of A and B, s-pair (t&1)
    const int r = tid >> 1;
    const int s0 = (tid & 1) * 2;
    const __half* ApR = A  + (size_t)(m0 + r) * GK;
    const __half* BpR = Bm + (size_t)(n0 + r) * GK;

    GemmLd L;
    {
        const int mt = r >> 4, rr = r & 15, gA = rr & 7, hi = rr >> 3;
        const int ntB = r >> 3, gB = r & 7;
#pragma unroll
        for (int js = 0; js < 2; js++) {
            int s = s0 + js;
#pragma unroll
            for (int hf = 0; hf < 2; hf++) {
                L.offA[js][hf] = ((mt * 4 + s) * 4 + hi + 2 * hf) * 128 + gA * 16;
                L.offB[js][hf] = B_REG_OFF + ((ntB * 4 + s) * 2 + hf) * 128 + gB * 16;
                L.gA[js][hf] = s * 16 + hf * 8;
                L.gB[js][hf] = s * 16 + hf * 8;
            }
        }
    }

    float acc[4][4][4];
#pragma unroll
    for (int i = 0; i < 4; i++)
#pragma unroll
        for (int j = 0; j < 4; j++)
#pragma unroll
            for (int q = 0; q < 4; q++) acc[i][j][q] = 0.f;

    gemm_issue(smb, 0, L, ApR, BpR);
    CP_COMMIT();
    gemm_issue(smb, 1, L, ApR, BpR);
    CP_COMMIT();

    const int mtg0 = wm >> 4;
    const int ntg0 = wn >> 3;

    for (int kt = 0; kt < NKT; kt++) {
        if (kt + 2 < NKT) gemm_issue(smb, kt + 2, L, ApR, BpR);
        CP_COMMIT();
        CP_WAIT(2);
        __syncthreads();

        const char* buf = sma + (kt % NSTAGE) * STAGE_BYTES;
#pragma unroll
        for (int s = 0; s < 4; s++) {
            uint32_t afr[4][4], bfr[4][2];
#pragma unroll
            for (int mt = 0; mt < 4; mt++) {
                const uint32_t* base = (const uint32_t*)(buf + ((mtg0 + mt) * 4 + s) * 4 * 128);
#pragma unroll
                for (int q = 0; q < 4; q++) afr[mt][q] = base[q * 32 + lane];
            }
#pragma unroll
            for (int nt = 0; nt < 4; nt++) {
                const uint32_t* base =
                    (const uint32_t*)(buf + B_REG_OFF + ((ntg0 + nt) * 4 + s) * 2 * 128);
#pragma unroll
                for (int q = 0; q < 2; q++) bfr[nt][q] = base[q * 32 + lane];
            }
#pragma unroll
            for (int mt = 0; mt < 4; mt++)
#pragma unroll
                for (int nt = 0; nt < 4; nt++)
                    mma_f16(acc[mt][nt], afr[mt], bfr[nt]);
        }
        __syncthreads();
    }

    const int g = lane >> 2;
    const int tg = lane & 3;
#pragma unroll
    for (int mt = 0; mt < 4; mt++) {
#pragma unroll
        for (int rh = 0; rh < 2; rh++) {
            const int m = m0 + wm + mt * 16 + g + rh * 8;
#pragma unroll
            for (int nt = 0; nt < 4; nt++) {
                const int n = n0 + wn + nt * 8 + tg * 2;
                float v0 = acc[mt][nt][rh * 2 + 0];
                float v1 = acc[mt][nt][rh * 2 + 1];
                if (MODE == 0) {
                    const int bb = m >> 11, ss = m & 2047;
                    const int hh = n >> 6,  dd = n & 63;
                    if (z < 2) {
                        __half* C = (z == 0) ? C0 : C1;
                        __half2 hv = __floats2half2_rn(v0, v1);
                        *(__half2*)&C[(((size_t)bb * NHEADS + hh) * SEQ + ss) * DHEAD + dd] = hv;
                    } else {  // V: transposed [B,H,D,S]
                        __half* C = C2;
                        size_t base = ((size_t)bb * NHEADS + hh) * DHEAD;
                        C[(base + dd) * SEQ + ss]     = __float2half_rn(v0);
                        C[(base + dd + 1) * SEQ + ss] = __float2half_rn(v1);
                    }
                } else {
                    float* dst = Cf + (size_t)m * EMB + n;
                    *(float2*)dst = make_float2(v0 + bias[n], v1 + bias[n + 1]);
                }
            }
        }
    }
}

// ===========================================================================
// fp16 tensor-core causal flash attention.
// CTA 256 Q rows, 8 warps x 32-row tile (MT=2). KV tiles of 64 double-buffered.
// K from [B,H,S,D]; V from [B,H,D,S] (pre-transposed) — both land frag-direct.
// P c-fragments map 1:1 onto A-fragments: no smem, no syncwarp for P.
// ===========================================================================
#define KTILE_B   8192
#define AK_OFF(p) ((p) * KTILE_B)
#define AV_OFF(p) (2 * KTILE_B + (p) * KTILE_B)
#define ATTN_SMEM (4 * KTILE_B)

__device__ __forceinline__ void attn_load_tile(uint32_t smb, int tid, int buf,
                                               const __half* kb, const __half* vtb, int jt) {
    const int r = tid >> 2;      // 0..63 (seq row for K, d row for Vt)
    const int s = tid & 3;
    const int nt = r >> 3, gg = r & 7;
    uint32_t kdst = smb + AK_OFF(buf) + ((nt * 4 + s) * 2) * 128 + gg * 16;
    uint32_t vdst = smb + AV_OFF(buf) + ((nt * 4 + s) * 2) * 128 + gg * 16;
    const __half* kg = kb + (size_t)r * DHEAD + s * 16;
    const __half* vg = vtb + (size_t)r * SEQ + jt * 64 + s * 16;
    cp16(kdst, kg);
    cp16(kdst + 128, kg + 8);
    cp16(vdst, vg);
    cp16(vdst + 128, vg + 8);
    CP_COMMIT();
}

__global__ __launch_bounds__(256) void attn_tc(const __half* __restrict__ Q,
                                               const __half* __restrict__ Kg,
                                               const __half* __restrict__ Vt,
                                               __half* __restrict__ ctx) {
    extern __shared__ char sma[];
    const uint32_t smb = smem_u32(sma);
    const int tid  = threadIdx.x;
    const int wid  = tid >> 5;
    const int lane = tid & 31;
    const int g    = lane >> 2;
    const int tg   = lane & 3;
    const int blkE = gridDim.x - 1 - blockIdx.x;
    const int h = blockIdx.y;
    const int b = blockIdx.z;
    const int wrow = blkE * 256 + wid * 32;

    const __half* qb  = Q  + (((size_t)b * NHEADS + h) * SEQ + wrow) * DHEAD;
    const __half* kb0 = Kg + (((size_t)b * NHEADS + h) * SEQ) * DHEAD;
    const __half* vtb = Vt + (((size_t)b * NHEADS + h) * DHEAD) * SEQ;

    // Q A-fragments (m16n8k16): qf[mt][s][4], pre-scaled by 1/sqrt(D)=0.125 (exact)
    uint32_t qf[2][4][4];
    {
        const __half2 sc = __floats2half2_rn(0.125f, 0.125f);
        const __half2* q2 = (const __half2*)qb;
#pragma unroll
        for (int mt = 0; mt < 2; mt++)
#pragma unroll
            for (int s = 0; s < 4; s++) {
                __half2 h0 = __hmul2(q2[(mt * 16 + g) * 32 + s * 8 + tg], sc);
                __half2 h1 = __hmul2(q2[(mt * 16 + g + 8) * 32 + s * 8 + tg], sc);
                __half2 h2 = __hmul2(q2[(mt * 16 + g) * 32 + s * 8 + tg + 4], sc);
                __half2 h3 = __hmul2(q2[(mt * 16 + g + 8) * 32 + s * 8 + tg + 4], sc);
                qf[mt][s][0] = *(uint32_t*)&h0;
                qf[mt][s][1] = *(uint32_t*)&h1;
                qf[mt][s][2] = *(uint32_t*)&h2;
                qf[mt][s][3] = *(uint32_t*)&h3;
            }
    }

    float oacc[2][8][4];
#pragma unroll
    for (int mt = 0; mt < 2; mt++)
#pragma unroll
        for (int nt = 0; nt < 8; nt++)
#pragma unroll
            for (int q = 0; q < 4; q++) oacc[mt][nt][q] = 0.f;
    float m_[2][2] = {{-1e30f, -1e30f}, {-1e30f, -1e30f}};
    float l_[2][2] = {{0.f, 0.f}, {0.f, 0.f}};

    const int nT = 4 * blkE + 4;
    attn_load_tile(smb, tid, 0, kb0, vtb, 0);

    for (int jt = 0; jt < nT; jt++) {
        const int p = jt & 1;
        if (jt + 1 < nT) {
            attn_load_tile(smb, tid, 1 - p, kb0 + (size_t)(jt + 1) * 64 * DHEAD, vtb, jt + 1);
            CP_WAIT(1);
        } else {
            CP_WAIT(0);
        }
        __syncthreads();

        if (jt * 64 <= wrow + 31) {
            const char* Ks = sma + AK_OFF(p);
            const char* Vs = sma + AV_OFF(p);

            // ---- S = Q K^T ----
            float sacc[2][8][4];
#pragma unroll
            for (int mt = 0; mt < 2; mt++)
#pragma unroll
                for (int nt = 0; nt < 8; nt++)
#pragma unroll
                    for (int q = 0; q < 4; q++) sacc[mt][nt][q] = 0.f;

#pragma unroll
            for (int s = 0; s < 4; s++) {
#pragma unroll
                for (int nt = 0; nt < 8; nt++) {
                    const uint32_t* base = (const uint32_t*)(Ks + ((nt * 4 + s) * 2) * 128);
                    uint32_t bb[2] = {base[lane], base[32 + lane]};
                    mma_f16(sacc[0][nt], qf[0][s], bb);
                    mma_f16(sacc[1][nt], qf[1][s], bb);
                }
            }

            // ---- causal mask ----
            if (jt * 64 + 63 > wrow) {
#pragma unroll
                for (int mt = 0; mt < 2; mt++)
#pragma unroll
                    for (int nt = 0; nt < 8; nt++) {
                        int colb = jt * 64 + nt * 8 + 2 * tg;
#pragma unroll
                        for (int rh = 0; rh < 2; rh++) {
                            int row = wrow + mt * 16 + g + 8 * rh;
                            if (colb > row)     sacc[mt][nt][rh * 2 + 0] = -1e30f;
                            if (colb + 1 > row) sacc[mt][nt][rh * 2 + 1] = -1e30f;
                        }
                    }
            }

            // ---- online softmax ----
#pragma unroll
            for (int mt = 0; mt < 2; mt++) {
                float rmax[2] = {-1e30f, -1e30f};
#pragma unroll
                for (int nt = 0; nt < 8; nt++)
#pragma unroll
                    for (int rh = 0; rh < 2; rh++)
                        rmax[rh] = fmaxf(rmax[rh],
                                         fmaxf(sacc[mt][nt][rh * 2], sacc[mt][nt][rh * 2 + 1]));
#pragma unroll
                for (int rh = 0; rh < 2; rh++) {
                    rmax[rh] = fmaxf(rmax[rh], __shfl_xor_sync(0xffffffffu, rmax[rh], 1));
                    rmax[rh] = fmaxf(rmax[rh], __shfl_xor_sync(0xffffffffu, rmax[rh], 2));
                }
                float alpha[2], rsum[2] = {0.f, 0.f};
#pragma unroll
                for (int rh = 0; rh < 2; rh++) {
                    float mnew = fmaxf(m_[mt][rh], rmax[rh]);
                    alpha[rh] = __expf(m_[mt][rh] - mnew);
                    m_[mt][rh] = mnew;
                }
#pragma unroll
                for (int nt = 0; nt < 8; nt++)
#pragma unroll
                    for (int rh = 0; rh < 2; rh++) {
                        float p0 = __expf(sacc[mt][nt][rh * 2 + 0] - m_[mt][rh]);
                        float p1 = __expf(sacc[mt][nt][rh * 2 + 1] - m_[mt][rh]);
                        sacc[mt][nt][rh * 2 + 0] = p0;
                        sacc[mt][nt][rh * 2 + 1] = p1;
                        rsum[rh] += p0 + p1;
                    }
#pragma unroll
                for (int rh = 0; rh < 2; rh++) {
                    rsum[rh] += __shfl_xor_sync(0xffffffffu, rsum[rh], 1);
                    rsum[rh] += __shfl_xor_sync(0xffffffffu, rsum[rh], 2);
                    l_[mt][rh] = l_[mt][rh] * alpha[rh] + rsum[rh];
                }
#pragma unroll
                for (int nt = 0; nt < 8; nt++)
#pragma unroll
                    for (int rh = 0; rh < 2; rh++) {
                        oacc[mt][nt][rh * 2 + 0] *= alpha[rh];
                        oacc[mt][nt][rh * 2 + 1] *= alpha[rh];
                    }
            }

            // ---- O += P V : P c-frags pack directly into A-frags ----
#pragma unroll
            for (int s = 0; s < 4; s++) {   // k16-step over the 64 seq cols
                uint32_t pa[2][4];
#pragma unroll
                for (int mt = 0; mt < 2; mt++) {
                    pa[mt][0] = pack2(sacc[mt][2 * s][0],     sacc[mt][2 * s][1]);
                    pa[mt][1] = pack2(sacc[mt][2 * s][2],     sacc[mt][2 * s][3]);
                    pa[mt][2] = pack2(sacc[mt][2 * s + 1][0], sacc[mt][2 * s + 1][1]);
                    pa[mt][3] = pack2(sacc[mt][2 * s + 1][2], sacc[mt][2 * s + 1][3]);
                }
#pragma unroll
                for (int ntd = 0; ntd < 8; ntd++) {
                    const uint32_t* base = (const uint32_t*)(Vs + ((ntd * 4 + s) * 2) * 128);
                    uint32_t bb[2] = {base[lane], base[32 + lane]};
                    mma_f16(oacc[0][ntd], pa[0], bb);
                    mma_f16(oacc[1][ntd], pa[1], bb);
                }
            }
        }
        __syncthreads();
    }

    // ---- epilogue: O / l -> ctx [B,S,E] fp16 ----
#pragma unroll
    for (int mt = 0; mt < 2; mt++) {
        float inv[2] = {1.f / l_[mt][0], 1.f / l_[mt][1]};
#pragma unroll
        for (int rh = 0; rh < 2; rh++) {
            const int r = wrow + mt * 16 + g + 8 * rh;
            __half* dst = ctx + ((size_t)b * SEQ + r) * EMB + h * DHEAD + 2 * tg;
#pragma unroll
            for (int nt = 0; nt < 8; nt++) {
                __half2 hv = __floats2half2_rn(oacc[mt][nt][rh * 2 + 0] * inv[rh],
                                               oacc[mt][nt][rh * 2 + 1] * inv[rh]);
                *(__half2*)(dst + nt * 8) = hv;
            }
        }
    }
}

// ---------------------------------------------------------------------------
extern "C" void kernel_launch(void* const* d_in, const int* in_sizes, int n_in,
                              void* d_out, int out_size) {
    const float* x  = (const float*)d_in[0];
    const float* Wk = (const float*)d_in[1];
    const float* Wq = (const float*)d_in[2];
    const float* Wv = (const float*)d_in[3];
    const float* Wu = (const float*)d_in[4];
    const float* bu = (const float*)d_in[5];
    float* out = (float*)d_out;

    __half *qp, *kp, *vp, *cp, *xh, *wk, *wq, *wv, *wu;
    cudaGetSymbolAddress((void**)&qp, g_q);
    cudaGetSymbolAddress((void**)&kp, g_k);
    cudaGetSymbolAddress((void**)&vp, g_v);
    cudaGetSymbolAddress((void**)&cp, g_ctx);
    cudaGetSymbolAddress((void**)&xh, g_xh);
    cudaGetSymbolAddress((void**)&wk, g_wk);
    cudaGetSymbolAddress((void**)&wq, g_wq);
    cudaGetSymbolAddress((void**)&wv, g_wv);
    cudaGetSymbolAddress((void**)&wu, g_wu);

    cudaFuncSetAttribute(gemm_tc<0>, cudaFuncAttributeMaxDynamicSharedMemorySize, GEMM_SMEM);
    cudaFuncSetAttribute(gemm_tc<1>, cudaFuncAttributeMaxDynamicSharedMemorySize, GEMM_SMEM);
    cudaFuncSetAttribute(attn_tc, cudaFuncAttributeMaxDynamicSharedMemorySize, ATTN_SMEM);

    preround<<<8192, 256>>>((const float4*)x, (const float4*)Wk, (const float4*)Wq,
                            (const float4*)Wv, (const float4*)Wu);

    dim3 gqkv(EMB / 128, (NBATCH * SEQ) / 128, 3);
    gemm_tc<0><<<gqkv, 256, GEMM_SMEM>>>(xh, wq, wk, wv, qp, kp, vp, nullptr, nullptr);

    attn_tc<<<dim3(SEQ / 256, NHEADS, NBATCH), 256, ATTN_SMEM>>>(qp, kp, vp, cp);

    dim3 go(EMB / 128, (NBATCH * SEQ) / 128, 1);
    gemm_tc<1><<<go, 256, GEMM_SMEM>>>(cp, wu, nullptr, nullptr,
                                       nullptr, nullptr, nullptr, out, bu);
}